// round 9
// baseline (speedup 1.0000x reference)
#include <cuda_runtime.h>

typedef unsigned long long u64;

#define TPB   128
#define NCOL  4096
#define VPT   32      // elements handled per thread... (actually 4096/128 = 32)
#define NPAIR 16
#define NWARP 4
#define KITER 16

// NOTE: with TPB=128 each thread owns 4096/128 = 32 elements = 16 f32x2 pairs?
// That doubles register pressure. Instead keep VPT=16 by processing the row with
// 128 threads x 32 elems? -- No: we deliberately keep VPT at 4096/TPB.
// 4096/128 = 32 elems/thread is too many registers (w+k = 64 regs).
// So: keep TPB=128 but have each thread own 16 elems and each CTA own HALF a row?
// That reintroduces cross-CTA reduction. Correct resolution: TPB=128, VPT=32 is
// too fat; therefore we use TPB=128 with VPT=32 REJECTED.
// ==> Final layout actually used below: TPB=128, each CTA processes ONE row,
// each thread 32 elems as 16 pairs, but khot is NOT kept in registers for all
// pairs; it is. (w2:32 regs + k2:32 regs = 64 -> occupancy 8 CTAs.) We instead
// cap occupancy at 8 and rely on ILP from 16 independent chains.
#undef VPT
#undef NPAIR
#define VPT   32
#define NPAIR 16

// ---- packed f32x2 helpers ----
__device__ __forceinline__ u64 pk2(float a, float b) {
    u64 r; asm("mov.b64 %0,{%1,%2};" : "=l"(r) : "f"(a), "f"(b)); return r;
}
__device__ __forceinline__ void upk2(u64 v, float& a, float& b) {
    asm("mov.b64 {%0,%1},%2;" : "=f"(a), "=f"(b) : "l"(v));
}
__device__ __forceinline__ u64 mul2(u64 a, u64 b) {
    u64 d; asm("mul.rn.f32x2 %0,%1,%2;" : "=l"(d) : "l"(a), "l"(b)); return d;
}
__device__ __forceinline__ u64 add2(u64 a, u64 b) {
    u64 d; asm("add.rn.f32x2 %0,%1,%2;" : "=l"(d) : "l"(a), "l"(b)); return d;
}
__device__ __forceinline__ u64 fma2(u64 a, u64 b, u64 c) {
    u64 d; asm("fma.rn.f32x2 %0,%1,%2,%3;" : "=l"(d) : "l"(a), "l"(b), "l"(c)); return d;
}
__device__ __forceinline__ float rcpf(float x) {
    float r; asm("rcp.approx.f32 %0,%1;" : "=f"(r) : "f"(x)); return r;
}

// One CTA (128 threads, 4 warps) per row of 4096; 32 elems/thread as 16 f32x2
// pairs. Per iteration:
//   S = block_sum(w); ninv = -1/S
//   noh = w * ninv; khot -= noh; w = fma(noh, w, w)
// Reduction: intra-thread packed tree -> 3 xor-shfls (lanes 0-3 hold the 4
// group sums) -> 16 smem partials -> barrier -> broadcast float4 reads.
__global__ __launch_bounds__(TPB, 8) void subset_op_kernel(
    const float* __restrict__ scores, const float* __restrict__ g,
    float* __restrict__ out)
{
    __shared__ __align__(16) float red_max[NWARP * 4];
    __shared__ __align__(16) float red_sum[2][NWARP * 4];

    const int tid  = threadIdx.x;
    const int lane = tid & 31;
    const int wid  = tid >> 5;
    const size_t base = (size_t)blockIdx.x * NCOL;

    const float4* sc4 = reinterpret_cast<const float4*>(scores + base);
    const float4* g4  = reinterpret_cast<const float4*>(g + base);

    // ---- load + perturb: s = scores + g (coalesced float4, 8 per thread) ----
    float s[VPT];
    #pragma unroll
    for (int j = 0; j < 8; j++) {
        float4 a = sc4[j * TPB + tid];
        float4 b = g4 [j * TPB + tid];
        s[4*j+0] = a.x + b.x; s[4*j+1] = a.y + b.y;
        s[4*j+2] = a.z + b.z; s[4*j+3] = a.w + b.w;
    }

    // ---- block max (one-time) ----
    float m = s[0];
    #pragma unroll
    for (int i = 1; i < VPT; i++) m = fmaxf(m, s[i]);
    m = fmaxf(m, __shfl_xor_sync(0xffffffffu, m, 16));
    m = fmaxf(m, __shfl_xor_sync(0xffffffffu, m, 8));
    m = fmaxf(m, __shfl_xor_sync(0xffffffffu, m, 4));
    if (lane < 4) red_max[wid * 4 + lane] = m;
    __syncthreads();
    {
        float4 r0 = *reinterpret_cast<const float4*>(&red_max[0]);
        float4 r1 = *reinterpret_cast<const float4*>(&red_max[4]);
        float4 r2 = *reinterpret_cast<const float4*>(&red_max[8]);
        float4 r3 = *reinterpret_cast<const float4*>(&red_max[12]);
        m = fmaxf(fmaxf(fmaxf(r0.x, r0.y), fmaxf(r0.z, r0.w)),
                  fmaxf(fmaxf(r1.x, r1.y), fmaxf(r1.z, r1.w)));
        m = fmaxf(m, fmaxf(fmaxf(fmaxf(r2.x, r2.y), fmaxf(r2.z, r2.w)),
                           fmaxf(fmaxf(r3.x, r3.y), fmaxf(r3.z, r3.w))));
    }

    // ---- w = exp(s - m): the ONLY transcendental ----
    u64 w2[NPAIR], k2[NPAIR];
    #pragma unroll
    for (int p = 0; p < NPAIR; p++) {
        w2[p] = pk2(__expf(s[2*p] - m), __expf(s[2*p+1] - m));
        k2[p] = pk2(0.f, 0.f);
    }

    const u64 NONE2 = pk2(-1.f, -1.f);

    // ---- block sum of w -> ninv2 = {-1/S, -1/S}; 1 barrier per iteration ----
    auto block_ninv = [&](int it) -> u64 {
        // intra-thread tree over 16 pairs (15 packed adds, depth 4)
        u64 t0 = add2(add2(w2[0],  w2[1]),  add2(w2[2],  w2[3]));
        u64 t1 = add2(add2(w2[4],  w2[5]),  add2(w2[6],  w2[7]));
        u64 t2 = add2(add2(w2[8],  w2[9]),  add2(w2[10], w2[11]));
        u64 t3 = add2(add2(w2[12], w2[13]), add2(w2[14], w2[15]));
        u64 tt = add2(add2(t0, t1), add2(t2, t3));
        float lo, hi; upk2(tt, lo, hi);
        float local = lo + hi;
        // 3-shfl partial reduce: lanes 0-3 hold the 4 group sums
        local += __shfl_xor_sync(0xffffffffu, local, 16);
        local += __shfl_xor_sync(0xffffffffu, local, 8);
        local += __shfl_xor_sync(0xffffffffu, local, 4);
        if (lane < 4) red_sum[it & 1][wid * 4 + lane] = local;
        __syncthreads();
        // broadcast read 16 partials, packed-summed (identical in all threads)
        const float* rs = red_sum[it & 1];
        float4 r0 = *reinterpret_cast<const float4*>(&rs[0]);
        float4 r1 = *reinterpret_cast<const float4*>(&rs[4]);
        float4 r2 = *reinterpret_cast<const float4*>(&rs[8]);
        float4 r3 = *reinterpret_cast<const float4*>(&rs[12]);
        u64 s0 = add2(pk2(r0.x, r0.y), pk2(r0.z, r0.w));
        u64 s1 = add2(pk2(r1.x, r1.y), pk2(r1.z, r1.w));
        u64 s2 = add2(pk2(r2.x, r2.y), pk2(r2.z, r2.w));
        u64 s3 = add2(pk2(r3.x, r3.y), pk2(r3.z, r3.w));
        u64 ss = add2(add2(s0, s1), add2(s2, s3));
        float sl, sh; upk2(ss, sl, sh);
        float ninv = rcpf(sl + sh);
        return pk2(-ninv, -ninv);
    };

    for (int it = 0; it < KITER - 1; it++) {
        u64 ninv2 = block_ninv(it);
        #pragma unroll
        for (int p = 0; p < NPAIR; p++) {
            u64 noh = mul2(w2[p], ninv2);        // -onehot
            k2[p]   = fma2(noh, NONE2, k2[p]);   // khot += onehot
            w2[p]   = fma2(noh, w2[p], w2[p]);   // w *= (1 - onehot)
        }
    }
    {   // last iteration: w update is dead
        u64 ninv2 = block_ninv(KITER - 1);
        #pragma unroll
        for (int p = 0; p < NPAIR; p++) {
            u64 noh = mul2(w2[p], ninv2);
            k2[p]   = fma2(noh, NONE2, k2[p]);
        }
    }

    // ---- store khot (coalesced float4) ----
    float4* o4 = reinterpret_cast<float4*>(out + base);
    #pragma unroll
    for (int j = 0; j < 8; j++) {
        float4 v;
        upk2(k2[2*j],     v.x, v.y);
        upk2(k2[2*j + 1], v.z, v.w);
        o4[j * TPB + tid] = v;
    }
}

extern "C" void kernel_launch(void* const* d_in, const int* in_sizes, int n_in,
                              void* d_out, int out_size) {
    const float* scores = (const float*)d_in[0];
    const float* g      = (const float*)d_in[1];
    float* out          = (float*)d_out;
    int rows = in_sizes[0] / NCOL;   // 4*2048 = 8192
    subset_op_kernel<<<rows, TPB>>>(scores, g, out);
}

// round 12
// speedup vs baseline: 1.4103x; 1.4103x over previous
#include <cuda_runtime.h>

typedef unsigned long long u64;

#define TPB   256
#define NCOL  4096
#define VPT   16      // elements per thread (4096 / 256)
#define NPAIR 8
#define NWARP 8
#define KITER 16

// ---- packed f32x2 helpers (ptxas never auto-fuses these from C++) ----
__device__ __forceinline__ u64 pk2(float a, float b) {
    u64 r; asm("mov.b64 %0,{%1,%2};" : "=l"(r) : "f"(a), "f"(b)); return r;
}
__device__ __forceinline__ void upk2(u64 v, float& a, float& b) {
    asm("mov.b64 {%0,%1},%2;" : "=f"(a), "=f"(b) : "l"(v));
}
__device__ __forceinline__ u64 mul2(u64 a, u64 b) {
    u64 d; asm("mul.rn.f32x2 %0,%1,%2;" : "=l"(d) : "l"(a), "l"(b)); return d;
}
__device__ __forceinline__ u64 add2(u64 a, u64 b) {
    u64 d; asm("add.rn.f32x2 %0,%1,%2;" : "=l"(d) : "l"(a), "l"(b)); return d;
}
__device__ __forceinline__ u64 fma2(u64 a, u64 b, u64 c) {
    u64 d; asm("fma.rn.f32x2 %0,%1,%2,%3;" : "=l"(d) : "l"(a), "l"(b), "l"(c)); return d;
}
__device__ __forceinline__ float rcpf(float x) {
    float r; asm("rcp.approx.f32 %0,%1;" : "=f"(r) : "f"(x)); return r;
}

// One CTA (256 threads) per row of 4096. w = exp(s - max) in registers
// (8 f32x2 pairs), khot accumulated in registers. Per iteration:
//   S = block_sum(w); ninv = -1/S
//   noh = w*ninv (= -onehot); khot -= noh; w = fma(noh, w, w)
// Reduction critical path (shortened vs R4): packed intra-thread tree ->
// 3 xor-shfls {16,8,4} (lanes 0-3 hold the 4 lane-group sums) -> 32 smem
// partials -> 1 barrier -> 8 broadcast float4 reads + packed add tree.
__global__ __launch_bounds__(TPB, 5) void subset_op_kernel(
    const float* __restrict__ scores, const float* __restrict__ g,
    float* __restrict__ out)
{
    __shared__ __align__(16) float red_max[NWARP * 4];
    __shared__ __align__(16) float red_sum[2][NWARP * 4];

    const int tid  = threadIdx.x;
    const int lane = tid & 31;
    const int wid  = tid >> 5;
    const size_t base = (size_t)blockIdx.x * NCOL;

    const float4* sc4 = reinterpret_cast<const float4*>(scores + base);
    const float4* g4  = reinterpret_cast<const float4*>(g + base);

    // ---- load + perturb: s = scores + g (coalesced float4) ----
    float s[VPT];
    #pragma unroll
    for (int j = 0; j < 4; j++) {
        float4 a = sc4[j * TPB + tid];
        float4 b = g4 [j * TPB + tid];
        s[4*j+0] = a.x + b.x; s[4*j+1] = a.y + b.y;
        s[4*j+2] = a.z + b.z; s[4*j+3] = a.w + b.w;
    }

    // ---- block max (one-time; 3-shfl partial + 32 partials) ----
    float m = s[0];
    #pragma unroll
    for (int i = 1; i < VPT; i++) m = fmaxf(m, s[i]);
    m = fmaxf(m, __shfl_xor_sync(0xffffffffu, m, 16));
    m = fmaxf(m, __shfl_xor_sync(0xffffffffu, m, 8));
    m = fmaxf(m, __shfl_xor_sync(0xffffffffu, m, 4));
    if (lane < 4) red_max[wid * 4 + lane] = m;
    __syncthreads();
    #pragma unroll
    for (int j = 0; j < 8; j++) {
        float4 r = *reinterpret_cast<const float4*>(&red_max[4 * j]);
        m = fmaxf(m, fmaxf(fmaxf(r.x, r.y), fmaxf(r.z, r.w)));
    }

    // ---- w = exp(s - m): the ONLY transcendental ----
    u64 w2[NPAIR], k2[NPAIR];
    #pragma unroll
    for (int p = 0; p < NPAIR; p++) {
        w2[p] = pk2(__expf(s[2*p] - m), __expf(s[2*p+1] - m));
        k2[p] = pk2(0.f, 0.f);
    }

    const u64 NONE2 = pk2(-1.f, -1.f);

    // ---- block sum of w -> ninv2 = {-1/S, -1/S}; 1 barrier per iteration ----
    auto block_ninv = [&](int it) -> u64 {
        // intra-thread packed tree (depth 3)
        u64 a0 = add2(w2[0], w2[1]);
        u64 a1 = add2(w2[2], w2[3]);
        u64 a2 = add2(w2[4], w2[5]);
        u64 a3 = add2(w2[6], w2[7]);
        a0 = add2(a0, a1); a2 = add2(a2, a3);
        a0 = add2(a0, a2);
        float lo, hi; upk2(a0, lo, hi);
        float local = lo + hi;
        // 3 shfls only: lanes 0-3 hold the 4 lane-group sums (groups by lane&3)
        local += __shfl_xor_sync(0xffffffffu, local, 16);
        local += __shfl_xor_sync(0xffffffffu, local, 8);
        local += __shfl_xor_sync(0xffffffffu, local, 4);
        if (lane < 4) red_sum[it & 1][wid * 4 + lane] = local;
        __syncthreads();
        // broadcast read of 32 partials, packed-summed (identical in all threads)
        const float* rs = red_sum[it & 1];
        u64 t0 = pk2(0.f, 0.f), t1 = pk2(0.f, 0.f);
        #pragma unroll
        for (int j = 0; j < 4; j++) {
            float4 r0 = *reinterpret_cast<const float4*>(&rs[8 * j]);
            float4 r1 = *reinterpret_cast<const float4*>(&rs[8 * j + 4]);
            t0 = add2(t0, add2(pk2(r0.x, r0.y), pk2(r0.z, r0.w)));
            t1 = add2(t1, add2(pk2(r1.x, r1.y), pk2(r1.z, r1.w)));
        }
        t0 = add2(t0, t1);
        float sl, sh; upk2(t0, sl, sh);
        float ninv = rcpf(sl + sh);
        return pk2(-ninv, -ninv);
    };

    for (int it = 0; it < KITER - 1; it++) {
        u64 ninv2 = block_ninv(it);
        #pragma unroll
        for (int p = 0; p < NPAIR; p++) {
            u64 noh = mul2(w2[p], ninv2);        // -onehot
            w2[p]   = fma2(noh, w2[p], w2[p]);   // w *= (1 - onehot)  (critical path)
            k2[p]   = fma2(noh, NONE2, k2[p]);   // khot += onehot     (off critical path)
        }
    }
    {   // last iteration: w update is dead
        u64 ninv2 = block_ninv(KITER - 1);
        #pragma unroll
        for (int p = 0; p < NPAIR; p++) {
            u64 noh = mul2(w2[p], ninv2);
            k2[p]   = fma2(noh, NONE2, k2[p]);
        }
    }

    // ---- store khot (coalesced float4) ----
    float4* o4 = reinterpret_cast<float4*>(out + base);
    #pragma unroll
    for (int j = 0; j < 4; j++) {
        float4 v;
        upk2(k2[2*j],     v.x, v.y);
        upk2(k2[2*j + 1], v.z, v.w);
        o4[j * TPB + tid] = v;
    }
}

extern "C" void kernel_launch(void* const* d_in, const int* in_sizes, int n_in,
                              void* d_out, int out_size) {
    const float* scores = (const float*)d_in[0];
    const float* g      = (const float*)d_in[1];
    float* out          = (float*)d_out;
    int rows = in_sizes[0] / NCOL;   // 4*2048 = 8192
    subset_op_kernel<<<rows, TPB>>>(scores, g, out);
}